// round 1
// baseline (speedup 1.0000x reference)
#include <cuda_runtime.h>
#include <cstdint>

#define MAXN 100000
#define DH   256
#define DIN  128

// Scratch (static device globals — no allocation allowed)
__device__ float g_dinv[MAXN];
__device__ float g_buf1[(size_t)MAXN * DH];
__device__ float g_buf2[(size_t)MAXN * DH];

// ---------------------------------------------------------------------------
// Degree / normalization: dinv[i] = rsqrt(1 + indegree(i))
// ---------------------------------------------------------------------------
__global__ void deg_init_kernel(float* dinv, int n) {
    int i = blockIdx.x * blockDim.x + threadIdx.x;
    if (i < n) dinv[i] = 1.0f;  // self loop
}

__global__ void deg_count_kernel(const int* __restrict__ edst, int e, float* dinv) {
    int i = blockIdx.x * blockDim.x + threadIdx.x;
    if (i < e) atomicAdd(&dinv[edst[i]], 1.0f);
}

__global__ void deg_finish_kernel(float* dinv, int n) {
    int i = blockIdx.x * blockDim.x + threadIdx.x;
    if (i < n) dinv[i] = rsqrtf(dinv[i]);
}

// ---------------------------------------------------------------------------
// SGEMM with fused row scaling:  C[m, :] = dinv[m] * (A[m, :] @ W)
// A: [M, K] row-major, W: [K, DH] row-major, C: [M, DH]
// Tile: BM=64, BN=64, BK=16, 256 threads, each computes 4x4.
// ---------------------------------------------------------------------------
template <int K>
__global__ void __launch_bounds__(256)
gemm_scaled_kernel(const float* __restrict__ A, const float* __restrict__ W,
                   const float* __restrict__ dinv, float* __restrict__ C, int M) {
    __shared__ float As[16][64];
    __shared__ float Bs[16][64];

    const int bm  = blockIdx.x * 64;
    const int bn  = blockIdx.y * 64;
    const int tid = threadIdx.x;
    const int tx  = tid & 15;   // 0..15 -> 4 cols each
    const int ty  = tid >> 4;   // 0..15 -> 4 rows each

    // A-tile load mapping: each thread loads one float4
    const int arow = tid >> 2;        // 0..63
    const int acol = (tid & 3) * 4;   // 0,4,8,12
    // W-tile load mapping
    const int brow = tid >> 4;        // 0..15
    const int bcol = (tid & 15) * 4;  // 0..60

    float acc[4][4];
#pragma unroll
    for (int i = 0; i < 4; i++)
#pragma unroll
        for (int j = 0; j < 4; j++) acc[i][j] = 0.0f;

    const int garow = bm + arow;
    const bool arow_ok = (garow < M);

    for (int k0 = 0; k0 < K; k0 += 16) {
        float4 av = make_float4(0.f, 0.f, 0.f, 0.f);
        if (arow_ok)
            av = *reinterpret_cast<const float4*>(&A[(size_t)garow * K + k0 + acol]);
        As[acol + 0][arow] = av.x;
        As[acol + 1][arow] = av.y;
        As[acol + 2][arow] = av.z;
        As[acol + 3][arow] = av.w;

        float4 bv = *reinterpret_cast<const float4*>(&W[(size_t)(k0 + brow) * DH + bn + bcol]);
        *reinterpret_cast<float4*>(&Bs[brow][bcol]) = bv;

        __syncthreads();

#pragma unroll
        for (int k = 0; k < 16; k++) {
            float4 a = *reinterpret_cast<const float4*>(&As[k][ty * 4]);
            float4 b = *reinterpret_cast<const float4*>(&Bs[k][tx * 4]);
            acc[0][0] = fmaf(a.x, b.x, acc[0][0]);
            acc[0][1] = fmaf(a.x, b.y, acc[0][1]);
            acc[0][2] = fmaf(a.x, b.z, acc[0][2]);
            acc[0][3] = fmaf(a.x, b.w, acc[0][3]);
            acc[1][0] = fmaf(a.y, b.x, acc[1][0]);
            acc[1][1] = fmaf(a.y, b.y, acc[1][1]);
            acc[1][2] = fmaf(a.y, b.z, acc[1][2]);
            acc[1][3] = fmaf(a.y, b.w, acc[1][3]);
            acc[2][0] = fmaf(a.z, b.x, acc[2][0]);
            acc[2][1] = fmaf(a.z, b.y, acc[2][1]);
            acc[2][2] = fmaf(a.z, b.z, acc[2][2]);
            acc[2][3] = fmaf(a.z, b.w, acc[2][3]);
            acc[3][0] = fmaf(a.w, b.x, acc[3][0]);
            acc[3][1] = fmaf(a.w, b.y, acc[3][1]);
            acc[3][2] = fmaf(a.w, b.z, acc[3][2]);
            acc[3][3] = fmaf(a.w, b.w, acc[3][3]);
        }
        __syncthreads();
    }

#pragma unroll
    for (int i = 0; i < 4; i++) {
        int r = bm + ty * 4 + i;
        if (r < M) {
            float s = dinv[r];
            float4 v = make_float4(acc[i][0] * s, acc[i][1] * s, acc[i][2] * s, acc[i][3] * s);
            *reinterpret_cast<float4*>(&C[(size_t)r * DH + bn + tx * 4]) = v;
        }
    }
}

// ---------------------------------------------------------------------------
// Copy B2 = B1 (self-loop message initialization), vectorized
// ---------------------------------------------------------------------------
__global__ void copy_kernel(const float4* __restrict__ in, float4* __restrict__ out, int n4) {
    int i = blockIdx.x * blockDim.x + threadIdx.x;
    if (i < n4) out[i] = in[i];
}

// ---------------------------------------------------------------------------
// Edge scatter: one warp per edge. out[dst, :] += h'[src, :]
// 256 floats/edge -> 2x float4 per lane, vectorized REDG.
// ---------------------------------------------------------------------------
__global__ void __launch_bounds__(256)
scatter_kernel(const float* __restrict__ hp, float* __restrict__ agg,
               const int* __restrict__ esrc, const int* __restrict__ edst, int e) {
    int warp = (blockIdx.x * blockDim.x + threadIdx.x) >> 5;
    int lane = threadIdx.x & 31;
    if (warp >= e) return;
    int s = esrc[warp];
    int d = edst[warp];
    const float4* in = reinterpret_cast<const float4*>(hp + (size_t)s * DH) + lane;
    float4*       op = reinterpret_cast<float4*>(agg + (size_t)d * DH) + lane;
    float4 v0 = in[0];
    float4 v1 = in[32];
    asm volatile("red.global.add.v4.f32 [%0], {%1,%2,%3,%4};"
                 :: "l"(op), "f"(v0.x), "f"(v0.y), "f"(v0.z), "f"(v0.w) : "memory");
    asm volatile("red.global.add.v4.f32 [%0], {%1,%2,%3,%4};"
                 :: "l"(op + 32), "f"(v1.x), "f"(v1.y), "f"(v1.z), "f"(v1.w) : "memory");
}

// ---------------------------------------------------------------------------
// Finalize: out[i, j] = relu(agg[i, j] * dinv[i] + b[j])
// ---------------------------------------------------------------------------
__global__ void finalize_kernel(const float4* __restrict__ agg, const float* __restrict__ dinv,
                                const float4* __restrict__ b, float4* __restrict__ out, int n) {
    int i = blockIdx.x * blockDim.x + threadIdx.x;
    int total = n * (DH / 4);
    if (i >= total) return;
    int row  = i / (DH / 4);
    int col4 = i - row * (DH / 4);
    float  s  = dinv[row];
    float4 v  = agg[i];
    float4 bb = b[col4];
    v.x = fmaxf(fmaf(v.x, s, bb.x), 0.0f);
    v.y = fmaxf(fmaf(v.y, s, bb.y), 0.0f);
    v.z = fmaxf(fmaf(v.z, s, bb.z), 0.0f);
    v.w = fmaxf(fmaf(v.w, s, bb.w), 0.0f);
    out[i] = v;
}

// ---------------------------------------------------------------------------
// Launch
// ---------------------------------------------------------------------------
extern "C" void kernel_launch(void* const* d_in, const int* in_sizes, int n_in,
                              void* d_out, int out_size) {
    const float* x  = (const float*)d_in[0];
    const int*   ei = (const int*)d_in[1];
    const float* W1 = (const float*)d_in[2];
    const float* b1 = (const float*)d_in[3];
    const float* W2 = (const float*)d_in[4];
    const float* b2 = (const float*)d_in[5];
    float* out = (float*)d_out;

    const int n = in_sizes[0] / DIN;
    const int e = in_sizes[1] / 2;
    const int* esrc = ei;
    const int* edst = ei + e;

    float *dinv, *buf1, *buf2;
    cudaGetSymbolAddress((void**)&dinv, g_dinv);
    cudaGetSymbolAddress((void**)&buf1, g_buf1);
    cudaGetSymbolAddress((void**)&buf2, g_buf2);

    const int T = 256;
    const int n_blk   = (n + T - 1) / T;
    const int e_blk   = (e + T - 1) / T;
    const int feat4   = n * (DH / 4);             // float4 count of a feature matrix
    const int f4_blk  = (feat4 + T - 1) / T;
    const int sc_blk  = (e + (T / 32) - 1) / (T / 32);  // 1 warp per edge
    dim3 gemm_grid((n + 63) / 64, DH / 64);

    // normalization
    deg_init_kernel<<<n_blk, T>>>(dinv, n);
    deg_count_kernel<<<e_blk, T>>>(edst, e, dinv);
    deg_finish_kernel<<<n_blk, T>>>(dinv, n);

    // ----- Layer 1 -----
    gemm_scaled_kernel<DIN><<<gemm_grid, T>>>(x, W1, dinv, buf1, n);          // buf1 = (x@W1)*dinv
    copy_kernel<<<f4_blk, T>>>((const float4*)buf1, (float4*)buf2, feat4);    // self loops
    scatter_kernel<<<sc_blk, T>>>(buf1, buf2, esrc, edst, e);                 // edges
    finalize_kernel<<<f4_blk, T>>>((const float4*)buf2, dinv, (const float4*)b1,
                                   (float4*)buf1, n);                          // buf1 = relu(...)

    // ----- Layer 2 -----
    gemm_scaled_kernel<DH><<<gemm_grid, T>>>(buf1, W2, dinv, buf2, n);        // buf2 = (h@W2)*dinv
    copy_kernel<<<f4_blk, T>>>((const float4*)buf2, (float4*)out, feat4);     // self loops
    scatter_kernel<<<sc_blk, T>>>(buf2, out, esrc, edst, e);                  // edges
    finalize_kernel<<<f4_blk, T>>>((const float4*)out, dinv, (const float4*)b2,
                                   (float4*)out, n);                           // in-place
}

// round 2
// speedup vs baseline: 1.3582x; 1.3582x over previous
#include <cuda_runtime.h>
#include <cstdint>

#define MAXN 100000
#define DH   256
#define DIN  128

// Scratch (static device globals — no allocation allowed)
__device__ float g_dinv[MAXN];
__device__ float g_buf1[(size_t)MAXN * DH];
__device__ float g_buf2[(size_t)MAXN * DH];

// ---------------------------------------------------------------------------
// Degree / normalization: dinv[i] = rsqrt(1 + indegree(i))
// ---------------------------------------------------------------------------
__global__ void deg_init_kernel(float* dinv, int n) {
    int i = blockIdx.x * blockDim.x + threadIdx.x;
    if (i < n) dinv[i] = 1.0f;  // self loop
}

__global__ void deg_count_kernel(const int* __restrict__ edst, int e, float* dinv) {
    int i = blockIdx.x * blockDim.x + threadIdx.x;
    if (i < e) atomicAdd(&dinv[edst[i]], 1.0f);
}

__global__ void deg_finish_kernel(float* dinv, int n) {
    int i = blockIdx.x * blockDim.x + threadIdx.x;
    if (i < n) dinv[i] = rsqrtf(dinv[i]);
}

// ---------------------------------------------------------------------------
// SGEMM with fused row scaling:  C[m, :] = dinv[m] * (A[m, :] @ W)
// BM=128, BN=128, BK=16, 256 threads, 8x8 per thread.
// As stored transposed [k][m] with padded stride to dodge bank conflicts.
// ---------------------------------------------------------------------------
#define BM 128
#define BN 128
#define BK 16
#define AS_STRIDE 132   // 128 + 4 pad (keeps float4 alignment: 132*4 % 16 == 0)

template <int K>
__global__ void __launch_bounds__(256, 2)
gemm_scaled_kernel(const float* __restrict__ A, const float* __restrict__ W,
                   const float* __restrict__ dinv, float* __restrict__ C, int M) {
    __shared__ float As[BK * AS_STRIDE];
    __shared__ float Bs[BK * BN];

    const int bm  = blockIdx.x * BM;
    const int bn  = blockIdx.y * BN;
    const int tid = threadIdx.x;
    const int tx  = tid & 15;    // 0..15 -> col block of 8
    const int ty  = tid >> 4;    // 0..15 -> row block of 8
    const int tm  = ty * 8;
    const int tn  = tx * 8;

    // A-tile load: 128 rows x 16 cols = 512 float4; 2 per thread.
    // thread t loads row (t>>1), cols (t&1)*8 .. +7 (two float4)
    const int arow  = tid >> 1;            // 0..127
    const int acol  = (tid & 1) * 8;       // 0 or 8
    const int garow = bm + arow;
    const bool arow_ok = (garow < M);

    // B-tile load: 16 rows x 128 cols = 512 float4; 2 per thread (idx, idx+256)
    float acc[8][8];
#pragma unroll
    for (int i = 0; i < 8; i++)
#pragma unroll
        for (int j = 0; j < 8; j++) acc[i][j] = 0.0f;

    for (int k0 = 0; k0 < K; k0 += BK) {
        // ---- load A tile (transposed into As[k][m]) ----
        float4 av0 = make_float4(0.f, 0.f, 0.f, 0.f);
        float4 av1 = make_float4(0.f, 0.f, 0.f, 0.f);
        if (arow_ok) {
            const float* ap = &A[(size_t)garow * K + k0 + acol];
            av0 = *reinterpret_cast<const float4*>(ap);
            av1 = *reinterpret_cast<const float4*>(ap + 4);
        }
        As[(acol + 0) * AS_STRIDE + arow] = av0.x;
        As[(acol + 1) * AS_STRIDE + arow] = av0.y;
        As[(acol + 2) * AS_STRIDE + arow] = av0.z;
        As[(acol + 3) * AS_STRIDE + arow] = av0.w;
        As[(acol + 4) * AS_STRIDE + arow] = av1.x;
        As[(acol + 5) * AS_STRIDE + arow] = av1.y;
        As[(acol + 6) * AS_STRIDE + arow] = av1.z;
        As[(acol + 7) * AS_STRIDE + arow] = av1.w;

        // ---- load B tile (direct, coalesced) ----
#pragma unroll
        for (int r = 0; r < 2; r++) {
            int idx  = tid + r * 256;      // 0..511
            int brow = idx >> 5;           // 0..15
            int bc4  = (idx & 31) * 4;     // 0..124
            float4 bv = *reinterpret_cast<const float4*>(
                &W[(size_t)(k0 + brow) * DH + bn + bc4]);
            *reinterpret_cast<float4*>(&Bs[brow * BN + bc4]) = bv;
        }

        __syncthreads();

#pragma unroll
        for (int k = 0; k < BK; k++) {
            float a[8], b[8];
            *reinterpret_cast<float4*>(&a[0]) = *reinterpret_cast<const float4*>(&As[k * AS_STRIDE + tm]);
            *reinterpret_cast<float4*>(&a[4]) = *reinterpret_cast<const float4*>(&As[k * AS_STRIDE + tm + 4]);
            *reinterpret_cast<float4*>(&b[0]) = *reinterpret_cast<const float4*>(&Bs[k * BN + tn]);
            *reinterpret_cast<float4*>(&b[4]) = *reinterpret_cast<const float4*>(&Bs[k * BN + tn + 4]);
#pragma unroll
            for (int i = 0; i < 8; i++)
#pragma unroll
                for (int j = 0; j < 8; j++)
                    acc[i][j] = fmaf(a[i], b[j], acc[i][j]);
        }
        __syncthreads();
    }

#pragma unroll
    for (int i = 0; i < 8; i++) {
        int r = bm + tm + i;
        if (r < M) {
            float s = dinv[r];
            float4 v0 = make_float4(acc[i][0] * s, acc[i][1] * s, acc[i][2] * s, acc[i][3] * s);
            float4 v1 = make_float4(acc[i][4] * s, acc[i][5] * s, acc[i][6] * s, acc[i][7] * s);
            float* cp = &C[(size_t)r * DH + bn + tn];
            *reinterpret_cast<float4*>(cp)     = v0;
            *reinterpret_cast<float4*>(cp + 4) = v1;
        }
    }
}

// ---------------------------------------------------------------------------
// Edge scatter: one warp per edge. agg[dst, :] += hp[src, :]
// ---------------------------------------------------------------------------
__global__ void __launch_bounds__(256)
scatter_kernel(const float* __restrict__ hp, float* __restrict__ agg,
               const int* __restrict__ esrc, const int* __restrict__ edst, int e) {
    int warp = (blockIdx.x * blockDim.x + threadIdx.x) >> 5;
    int lane = threadIdx.x & 31;
    if (warp >= e) return;
    int s = esrc[warp];
    int d = edst[warp];
    const float4* in = reinterpret_cast<const float4*>(hp + (size_t)s * DH) + lane;
    float4*       op = reinterpret_cast<float4*>(agg + (size_t)d * DH) + lane;
    float4 v0 = __ldg(in);
    float4 v1 = __ldg(in + 32);
    asm volatile("red.global.add.v4.f32 [%0], {%1,%2,%3,%4};"
                 :: "l"(op), "f"(v0.x), "f"(v0.y), "f"(v0.z), "f"(v0.w) : "memory");
    asm volatile("red.global.add.v4.f32 [%0], {%1,%2,%3,%4};"
                 :: "l"(op + 32), "f"(v1.x), "f"(v1.y), "f"(v1.z), "f"(v1.w) : "memory");
}

// ---------------------------------------------------------------------------
// Finalize (self-loop fused): out[i,j] = relu((agg[i,j] + hp[i,j]) * dinv[i] + b[j])
// ---------------------------------------------------------------------------
__global__ void finalize_kernel(const float4* __restrict__ agg, const float4* __restrict__ hp,
                                const float* __restrict__ dinv, const float4* __restrict__ b,
                                float4* __restrict__ out, int n) {
    int i = blockIdx.x * blockDim.x + threadIdx.x;
    int total = n * (DH / 4);
    if (i >= total) return;
    int row  = i / (DH / 4);
    int col4 = i - row * (DH / 4);
    float  s  = dinv[row];
    float4 v  = agg[i];
    float4 h  = hp[i];
    float4 bb = b[col4];
    v.x = fmaxf(fmaf(v.x + h.x, s, bb.x), 0.0f);
    v.y = fmaxf(fmaf(v.y + h.y, s, bb.y), 0.0f);
    v.z = fmaxf(fmaf(v.z + h.z, s, bb.z), 0.0f);
    v.w = fmaxf(fmaf(v.w + h.w, s, bb.w), 0.0f);
    out[i] = v;
}

// ---------------------------------------------------------------------------
// Launch
// ---------------------------------------------------------------------------
extern "C" void kernel_launch(void* const* d_in, const int* in_sizes, int n_in,
                              void* d_out, int out_size) {
    const float* x  = (const float*)d_in[0];
    const int*   ei = (const int*)d_in[1];
    const float* W1 = (const float*)d_in[2];
    const float* b1 = (const float*)d_in[3];
    const float* W2 = (const float*)d_in[4];
    const float* b2 = (const float*)d_in[5];
    float* out = (float*)d_out;

    const int n = in_sizes[0] / DIN;
    const int e = in_sizes[1] / 2;
    const int* esrc = ei;
    const int* edst = ei + e;

    float *dinv, *buf1, *buf2;
    cudaGetSymbolAddress((void**)&dinv, g_dinv);
    cudaGetSymbolAddress((void**)&buf1, g_buf1);
    cudaGetSymbolAddress((void**)&buf2, g_buf2);

    const size_t feat_bytes = (size_t)n * DH * sizeof(float);
    const int T = 256;
    const int n_blk  = (n + T - 1) / T;
    const int e_blk  = (e + T - 1) / T;
    const int feat4  = n * (DH / 4);
    const int f4_blk = (feat4 + T - 1) / T;
    const int sc_blk = (e + (T / 32) - 1) / (T / 32);
    dim3 gemm_grid((n + BM - 1) / BM, DH / BN);

    // normalization
    deg_init_kernel<<<n_blk, T>>>(dinv, n);
    deg_count_kernel<<<e_blk, T>>>(edst, e, dinv);
    deg_finish_kernel<<<n_blk, T>>>(dinv, n);

    // ----- Layer 1 -----
    gemm_scaled_kernel<DIN><<<gemm_grid, T>>>(x, W1, dinv, buf1, n);   // buf1 = (x@W1)*dinv
    cudaMemsetAsync(buf2, 0, feat_bytes);                               // agg = 0
    scatter_kernel<<<sc_blk, T>>>(buf1, buf2, esrc, edst, e);           // edges
    finalize_kernel<<<f4_blk, T>>>((const float4*)buf2, (const float4*)buf1, dinv,
                                   (const float4*)b1, (float4*)buf1, n);  // buf1 = relu(...)

    // ----- Layer 2 -----
    gemm_scaled_kernel<DH><<<gemm_grid, T>>>(buf1, W2, dinv, buf2, n); // buf2 = (h@W2)*dinv
    cudaMemsetAsync(out, 0, feat_bytes);                                // agg = 0
    scatter_kernel<<<sc_blk, T>>>(buf2, out, esrc, edst, e);            // edges
    finalize_kernel<<<f4_blk, T>>>((const float4*)out, (const float4*)buf2, dinv,
                                   (const float4*)b2, (float4*)out, n);   // in-place
}

// round 3
// speedup vs baseline: 2.0737x; 1.5268x over previous
#include <cuda_runtime.h>
#include <cstdint>

#define MAXN  100000
#define MAXE  2000000
#define DH    256
#define DIN   128

// Scratch (static device globals — no allocation allowed)
__device__ float g_dinv[MAXN];
__device__ float g_buf1[(size_t)MAXN * DH];
__device__ float g_buf2[(size_t)MAXN * DH];
__device__ int   g_cnt[MAXN];
__device__ int   g_off[MAXN + 1];
__device__ int   g_cur[MAXN];
__device__ int   g_src[MAXE];

// ---------------------------------------------------------------------------
// CSR build: indegree count
// ---------------------------------------------------------------------------
__global__ void count_kernel(const int* __restrict__ edst, int e, int* __restrict__ cnt) {
    int i = blockIdx.x * blockDim.x + threadIdx.x;
    if (i < e) atomicAdd(&cnt[edst[i]], 1);
}

// Single-block chunked exclusive scan over cnt[0..n) -> off, cursor; also dinv.
__global__ void __launch_bounds__(1024)
scan_kernel(const int* __restrict__ cnt, int* __restrict__ off, int* __restrict__ cur,
            float* __restrict__ dinv, int n) {
    __shared__ int ssum[1024];
    const int tid = threadIdx.x;
    const int chunk = (n + 1023) >> 10;
    const int begin = tid * chunk;
    const int end   = min(begin + chunk, n);

    int mysum = 0;
    for (int i = begin; i < end; i++) mysum += cnt[i];
    ssum[tid] = mysum;
    __syncthreads();

    // Hillis-Steele inclusive scan
    for (int d = 1; d < 1024; d <<= 1) {
        int add = (tid >= d) ? ssum[tid - d] : 0;
        __syncthreads();
        ssum[tid] += add;
        __syncthreads();
    }

    int run = ssum[tid] - mysum;  // exclusive base for this chunk
    for (int i = begin; i < end; i++) {
        int c = cnt[i];
        off[i] = run;
        cur[i] = run;
        dinv[i] = rsqrtf(1.0f + (float)c);
        run += c;
    }
    if (tid == 1023) off[n] = ssum[1023];
}

__global__ void fill_kernel(const int* __restrict__ esrc, const int* __restrict__ edst,
                            int e, int* __restrict__ cur, int* __restrict__ sorted) {
    int i = blockIdx.x * blockDim.x + threadIdx.x;
    if (i < e) {
        int d = edst[i];
        int pos = atomicAdd(&cur[d], 1);
        sorted[pos] = esrc[i];
    }
}

// ---------------------------------------------------------------------------
// SGEMM with fused row scaling:  C[m, :] = dinv[m] * (A[m, :] @ W)
// BM=128, BN=128, BK=16, 256 threads, 8x8/thread.
// Double-buffered: B via cp.async.cg, A via register prefetch (transposed store).
// ---------------------------------------------------------------------------
#define BM 128
#define BN 128
#define BK 16
#define AS_STRIDE 132

__device__ __forceinline__ void cp_async16(void* smem_dst, const void* gmem_src) {
    uint32_t s = (uint32_t)__cvta_generic_to_shared(smem_dst);
    asm volatile("cp.async.cg.shared.global [%0], [%1], 16;\n" :: "r"(s), "l"(gmem_src));
}
__device__ __forceinline__ void cp_async_commit() {
    asm volatile("cp.async.commit_group;\n");
}
__device__ __forceinline__ void cp_async_wait0() {
    asm volatile("cp.async.wait_group 0;\n" ::: "memory");
}

template <int K>
__global__ void __launch_bounds__(256, 2)
gemm_scaled_kernel(const float* __restrict__ A, const float* __restrict__ W,
                   const float* __restrict__ dinv, float* __restrict__ C, int M) {
    constexpr int NT = K / BK;
    __shared__ float As[2][BK * AS_STRIDE];
    __shared__ float Bs[2][BK * BN];

    const int bm  = blockIdx.x * BM;
    const int bn  = blockIdx.y * BN;
    const int tid = threadIdx.x;
    const int tx  = tid & 15;
    const int ty  = tid >> 4;
    const int tm  = ty * 8;
    const int tn  = tx * 8;

    // A-tile load mapping: thread loads row (tid>>1), 8 cols starting (tid&1)*8
    const int arow  = tid >> 1;
    const int acol  = (tid & 1) * 8;
    const int garow = bm + arow;
    const bool arow_ok = (garow < M);
    const float* aptr = arow_ok ? &A[(size_t)garow * K + acol] : nullptr;

    // B-tile load mapping: two 16B slots per thread
    const int brow0 = tid >> 5;           // 0..7
    const int bc0   = (tid & 31) * 4;     // 0..124
    const int brow1 = brow0 + 8;          // 8..15
    const float* wptr0 = &W[(size_t)brow0 * DH + bn + bc0];
    const float* wptr1 = &W[(size_t)brow1 * DH + bn + bc0];

    float acc[8][8];
#pragma unroll
    for (int i = 0; i < 8; i++)
#pragma unroll
        for (int j = 0; j < 8; j++) acc[i][j] = 0.0f;

    // ---- prologue: tile 0 ----
    {
        float4 av0 = make_float4(0.f, 0.f, 0.f, 0.f);
        float4 av1 = make_float4(0.f, 0.f, 0.f, 0.f);
        if (arow_ok) {
            av0 = *reinterpret_cast<const float4*>(aptr);
            av1 = *reinterpret_cast<const float4*>(aptr + 4);
        }
        float* as = &As[0][0];
        as[(acol + 0) * AS_STRIDE + arow] = av0.x;
        as[(acol + 1) * AS_STRIDE + arow] = av0.y;
        as[(acol + 2) * AS_STRIDE + arow] = av0.z;
        as[(acol + 3) * AS_STRIDE + arow] = av0.w;
        as[(acol + 4) * AS_STRIDE + arow] = av1.x;
        as[(acol + 5) * AS_STRIDE + arow] = av1.y;
        as[(acol + 6) * AS_STRIDE + arow] = av1.z;
        as[(acol + 7) * AS_STRIDE + arow] = av1.w;
        cp_async16(&Bs[0][brow0 * BN + bc0], wptr0);
        cp_async16(&Bs[0][brow1 * BN + bc0], wptr1);
        cp_async_commit();
        cp_async_wait0();
        __syncthreads();
    }

    for (int t = 0; t < NT; t++) {
        const int curb = t & 1;
        const int nxtb = curb ^ 1;
        float4 av0, av1;
        const bool has_next = (t + 1 < NT);

        if (has_next) {
            const int k0 = (t + 1) * BK;
            av0 = make_float4(0.f, 0.f, 0.f, 0.f);
            av1 = make_float4(0.f, 0.f, 0.f, 0.f);
            if (arow_ok) {
                av0 = *reinterpret_cast<const float4*>(aptr + k0);
                av1 = *reinterpret_cast<const float4*>(aptr + k0 + 4);
            }
            cp_async16(&Bs[nxtb][brow0 * BN + bc0], wptr0 + (size_t)k0 * DH);
            cp_async16(&Bs[nxtb][brow1 * BN + bc0], wptr1 + (size_t)k0 * DH);
            cp_async_commit();
        }

        const float* as = &As[curb][0];
        const float* bs = &Bs[curb][0];
#pragma unroll
        for (int k = 0; k < BK; k++) {
            float a[8], b[8];
            *reinterpret_cast<float4*>(&a[0]) = *reinterpret_cast<const float4*>(&as[k * AS_STRIDE + tm]);
            *reinterpret_cast<float4*>(&a[4]) = *reinterpret_cast<const float4*>(&as[k * AS_STRIDE + tm + 4]);
            *reinterpret_cast<float4*>(&b[0]) = *reinterpret_cast<const float4*>(&bs[k * BN + tn]);
            *reinterpret_cast<float4*>(&b[4]) = *reinterpret_cast<const float4*>(&bs[k * BN + tn + 4]);
#pragma unroll
            for (int i = 0; i < 8; i++)
#pragma unroll
                for (int j = 0; j < 8; j++)
                    acc[i][j] = fmaf(a[i], b[j], acc[i][j]);
        }

        if (has_next) {
            float* asn = &As[nxtb][0];
            asn[(acol + 0) * AS_STRIDE + arow] = av0.x;
            asn[(acol + 1) * AS_STRIDE + arow] = av0.y;
            asn[(acol + 2) * AS_STRIDE + arow] = av0.z;
            asn[(acol + 3) * AS_STRIDE + arow] = av0.w;
            asn[(acol + 4) * AS_STRIDE + arow] = av1.x;
            asn[(acol + 5) * AS_STRIDE + arow] = av1.y;
            asn[(acol + 6) * AS_STRIDE + arow] = av1.z;
            asn[(acol + 7) * AS_STRIDE + arow] = av1.w;
            cp_async_wait0();
            __syncthreads();
        }
    }

#pragma unroll
    for (int i = 0; i < 8; i++) {
        int r = bm + tm + i;
        if (r < M) {
            float s = dinv[r];
            float4 v0 = make_float4(acc[i][0] * s, acc[i][1] * s, acc[i][2] * s, acc[i][3] * s);
            float4 v1 = make_float4(acc[i][4] * s, acc[i][5] * s, acc[i][6] * s, acc[i][7] * s);
            float* cp = &C[(size_t)r * DH + bn + tn];
            *reinterpret_cast<float4*>(cp)     = v0;
            *reinterpret_cast<float4*>(cp + 4) = v1;
        }
    }
}

// ---------------------------------------------------------------------------
// Gather (CSR by destination) + self-loop + finalize:
//   out[d, :] = relu((hp[d, :] + sum_{s in N(d)} hp[s, :]) * dinv[d] + b)
// One warp per destination node; each lane owns 2 float4 (8 floats).
// ---------------------------------------------------------------------------
__global__ void __launch_bounds__(256)
gather_kernel(const float* __restrict__ hp, const int* __restrict__ off,
              const int* __restrict__ sorted, const float* __restrict__ dinv,
              const float* __restrict__ b, float* __restrict__ out, int n) {
    int warp = (blockIdx.x * blockDim.x + threadIdx.x) >> 5;
    int lane = threadIdx.x & 31;
    if (warp >= n) return;
    const int d  = warp;
    const int s0 = off[d];
    const int s1 = off[d + 1];

    const float4* self = reinterpret_cast<const float4*>(hp + (size_t)d * DH) + lane;
    float4 v0 = __ldg(self);
    float4 v1 = __ldg(self + 32);

    int j = s0;
    int snext = (j < s1) ? __ldg(&sorted[j]) : 0;
    for (; j < s1; j++) {
        int s = snext;
        if (j + 1 < s1) snext = __ldg(&sorted[j + 1]);
        const float4* in = reinterpret_cast<const float4*>(hp + (size_t)s * DH) + lane;
        float4 a = __ldg(in);
        float4 c = __ldg(in + 32);
        v0.x += a.x; v0.y += a.y; v0.z += a.z; v0.w += a.w;
        v1.x += c.x; v1.y += c.y; v1.z += c.z; v1.w += c.w;
    }

    const float sc = dinv[d];
    const float4 bb0 = __ldg(reinterpret_cast<const float4*>(b) + lane);
    const float4 bb1 = __ldg(reinterpret_cast<const float4*>(b) + lane + 32);
    v0.x = fmaxf(fmaf(v0.x, sc, bb0.x), 0.0f);
    v0.y = fmaxf(fmaf(v0.y, sc, bb0.y), 0.0f);
    v0.z = fmaxf(fmaf(v0.z, sc, bb0.z), 0.0f);
    v0.w = fmaxf(fmaf(v0.w, sc, bb0.w), 0.0f);
    v1.x = fmaxf(fmaf(v1.x, sc, bb1.x), 0.0f);
    v1.y = fmaxf(fmaf(v1.y, sc, bb1.y), 0.0f);
    v1.z = fmaxf(fmaf(v1.z, sc, bb1.z), 0.0f);
    v1.w = fmaxf(fmaf(v1.w, sc, bb1.w), 0.0f);

    float4* op = reinterpret_cast<float4*>(out + (size_t)d * DH) + lane;
    op[0]  = v0;
    op[32] = v1;
}

// ---------------------------------------------------------------------------
// Launch
// ---------------------------------------------------------------------------
extern "C" void kernel_launch(void* const* d_in, const int* in_sizes, int n_in,
                              void* d_out, int out_size) {
    const float* x  = (const float*)d_in[0];
    const int*   ei = (const int*)d_in[1];
    const float* W1 = (const float*)d_in[2];
    const float* b1 = (const float*)d_in[3];
    const float* W2 = (const float*)d_in[4];
    const float* b2 = (const float*)d_in[5];
    float* out = (float*)d_out;

    const int n = in_sizes[0] / DIN;
    const int e = in_sizes[1] / 2;
    const int* esrc = ei;
    const int* edst = ei + e;

    float *dinv, *buf1, *buf2;
    int *cnt, *off, *cur, *srt;
    cudaGetSymbolAddress((void**)&dinv, g_dinv);
    cudaGetSymbolAddress((void**)&buf1, g_buf1);
    cudaGetSymbolAddress((void**)&buf2, g_buf2);
    cudaGetSymbolAddress((void**)&cnt,  g_cnt);
    cudaGetSymbolAddress((void**)&off,  g_off);
    cudaGetSymbolAddress((void**)&cur,  g_cur);
    cudaGetSymbolAddress((void**)&srt,  g_src);

    const int T = 256;
    const int e_blk = (e + T - 1) / T;
    const int g_blk = (n + (T / 32) - 1) / (T / 32);  // 1 warp per node
    dim3 gemm_grid((n + BM - 1) / BM, DH / BN);

    // ----- CSR build (once, reused by both layers) -----
    cudaMemsetAsync(cnt, 0, (size_t)n * sizeof(int));
    count_kernel<<<e_blk, T>>>(edst, e, cnt);
    scan_kernel<<<1, 1024>>>(cnt, off, cur, dinv, n);
    fill_kernel<<<e_blk, T>>>(esrc, edst, e, cur, srt);

    // ----- Layer 1 -----
    gemm_scaled_kernel<DIN><<<gemm_grid, T>>>(x, W1, dinv, buf1, n);      // buf1 = (x@W1)*dinv
    gather_kernel<<<g_blk, T>>>(buf1, off, srt, dinv, b1, buf2, n);       // buf2 = relu(...)

    // ----- Layer 2 -----
    gemm_scaled_kernel<DH><<<gemm_grid, T>>>(buf2, W2, dinv, buf1, n);    // buf1 = (h@W2)*dinv
    gather_kernel<<<g_blk, T>>>(buf1, off, srt, dinv, b2, out, n);        // out = relu(...)
}